// round 12
// baseline (speedup 1.0000x reference)
#include <cuda_runtime.h>
#include <cuda_fp16.h>
#include <cuda_bf16.h>
#include <mma.h>

using namespace nvcuda;

#define MAX_NODES 100000
#define MAX_EDGES 640000
// g_src capacity: edges + up-to-3 pad slots per node (16B-aligned regions)
#define SRC_CAP (MAX_EDGES + 4 * MAX_NODES)

// Scratch (device globals — allocation in kernel_launch is forbidden).
// NOTE: g_hist must be all-zero at kernel_launch entry. It is zero-initialized
// at module load, and the fused kernel restores it to zero every call.
__device__ __half g_Xh[(size_t)MAX_NODES * 128];        // X in fp16 (25.6 MB)
__device__ int    g_hist[MAX_NODES + 256];              // counts; [N+1] = base counter
__device__ int2   g_meta[MAX_NODES];                    // {aligned start, count}
__device__ int    g_cursor[MAX_NODES];
__device__ int    g_src[SRC_CAP];                       // sources grouped by dest

// Static-initializer stream/event creation (host-side).
struct SideStream {
    cudaStream_t s;
    cudaEvent_t fork, join;
    SideStream() {
        cudaStreamCreateWithFlags(&s, cudaStreamNonBlocking);
        cudaEventCreateWithFlags(&fork, cudaEventDisableTiming);
        cudaEventCreateWithFlags(&join, cudaEventDisableTiming);
    }
};
static SideStream g_ss;

// ---------------------------------------------------------------------------
// X -> fp16 convert (streaming; runs concurrently with the sort chain)
// ---------------------------------------------------------------------------
__global__ void convert_kernel(const float* __restrict__ X, int total4) {
    int i = blockIdx.x * blockDim.x + threadIdx.x;
    if (i < total4) {
        float4 v = ((const float4*)X)[i];
        __half2 h0 = __floats2half2_rn(v.x, v.y);
        __half2 h1 = __floats2half2_rn(v.z, v.w);
        uint2 u;
        u.x = *(unsigned*)&h0;
        u.y = *(unsigned*)&h1;
        ((uint2*)g_Xh)[i] = u;
    }
}

// ---------------------------------------------------------------------------
// Sort phase 1: histogram of destinations (8 edges/thread for atomic MLP)
// ---------------------------------------------------------------------------
__global__ void hist_kernel(const int* __restrict__ refB, int E) {
    int base = (blockIdx.x * blockDim.x + threadIdx.x) * 8;
    if (base + 7 < E) {
        int4 d0 = *(const int4*)(refB + base);
        int4 d1 = *(const int4*)(refB + base + 4);
        atomicAdd(&g_hist[d0.x], 1);
        atomicAdd(&g_hist[d0.y], 1);
        atomicAdd(&g_hist[d0.z], 1);
        atomicAdd(&g_hist[d0.w], 1);
        atomicAdd(&g_hist[d1.x], 1);
        atomicAdd(&g_hist[d1.y], 1);
        atomicAdd(&g_hist[d1.z], 1);
        atomicAdd(&g_hist[d1.w], 1);
    } else {
        for (int i = base; i < E; i++) atomicAdd(&g_hist[refB[i]], 1);
    }
}

// ---------------------------------------------------------------------------
// Sort phase 2 (fused scan): counts padded to multiples of 4 (16B-aligned
// regions); block total claims a base via atomicAdd on g_hist[N+1].
// ---------------------------------------------------------------------------
__global__ __launch_bounds__(256)
void scan_fused_kernel(int N) {
    __shared__ int warp_pref[8];
    __shared__ int block_base;
    int t = threadIdx.x, lane = t & 31, wid = t >> 5;
    int node = blockIdx.x * 256 + t;
    int v = (node < N) ? g_hist[node] : 0;
    int vp = (v + 3) & ~3;

    int x = vp;
#pragma unroll
    for (int off = 1; off < 32; off <<= 1) {
        int y = __shfl_up_sync(0xFFFFFFFFu, x, off);
        if (lane >= off) x += y;
    }
    if (lane == 31) warp_pref[wid] = x;
    __syncthreads();
    if (wid == 0) {
        int ws = (lane < 8) ? warp_pref[lane] : 0;
        int wx = ws;
#pragma unroll
        for (int off = 1; off < 8; off <<= 1) {
            int y = __shfl_up_sync(0xFFFFFFFFu, wx, off);
            if (lane >= off) wx += y;
        }
        if (lane < 8) warp_pref[lane] = wx - ws;
        if (lane == 7) block_base = atomicAdd(&g_hist[N + 1], wx);
    }
    __syncthreads();
    if (node < N) {
        int start = block_base + warp_pref[wid] + x - vp;
        g_meta[node]   = make_int2(start, v);
        g_cursor[node] = start;
    }
}

// ---------------------------------------------------------------------------
// Sort phase 3: bucket reorder (8 edges/thread for atomic MLP)
// ---------------------------------------------------------------------------
__global__ void reorder_kernel(const int* __restrict__ refA,
                               const int* __restrict__ refB, int E) {
    int base = (blockIdx.x * blockDim.x + threadIdx.x) * 8;
    if (base + 7 < E) {
        int4 d0 = *(const int4*)(refB + base);
        int4 d1 = *(const int4*)(refB + base + 4);
        int4 a0 = *(const int4*)(refA + base);
        int4 a1 = *(const int4*)(refA + base + 4);
        int p0 = atomicAdd(&g_cursor[d0.x], 1);
        int p1 = atomicAdd(&g_cursor[d0.y], 1);
        int p2 = atomicAdd(&g_cursor[d0.z], 1);
        int p3 = atomicAdd(&g_cursor[d0.w], 1);
        int p4 = atomicAdd(&g_cursor[d1.x], 1);
        int p5 = atomicAdd(&g_cursor[d1.y], 1);
        int p6 = atomicAdd(&g_cursor[d1.z], 1);
        int p7 = atomicAdd(&g_cursor[d1.w], 1);
        g_src[p0] = a0.x;
        g_src[p1] = a0.y;
        g_src[p2] = a0.z;
        g_src[p3] = a0.w;
        g_src[p4] = a1.x;
        g_src[p5] = a1.y;
        g_src[p6] = a1.z;
        g_src[p7] = a1.w;
    } else {
        for (int i = base; i < E; i++) {
            int pos = atomicAdd(&g_cursor[refB[i]], 1);
            g_src[pos] = refA[i];
        }
    }
}

// ---------------------------------------------------------------------------
// FUSED aggregate + GEMM + bias:
//   out[n,:] = (sum over incoming edges of Xh[src,:]) @ W + b
// Persistent blocks grid-stride over 64-node tiles.
//   Phase A: each warp aggregates 8 nodes (fp16 gather -> fp32 regs), writes
//            the 64x128 agg tile to smem as fp16.
//   Phase B: 8-warp wmma GEMM (agg @ W), epilogue adds bias, fp32 out.
// ---------------------------------------------------------------------------
#define LDH 136   // padded leading dim (halves)
#define SW_HALFS   (128 * LDH)
#define SA_HALFS   (64 * LDH)
#define FUSED_SMEM_BYTES ((SW_HALFS + SA_HALFS) * 2)

__global__ __launch_bounds__(256, 2)
void fused_kernel(const float* __restrict__ W,
                  const float* __restrict__ bias,
                  float* __restrict__ out,
                  int n_tiles, int N) {
    extern __shared__ __half smem[];
    __half* sW   = smem;               // 128 x LDH
    __half* sAgg = smem + SW_HALFS;    // 64 x LDH (reused as fp32 epi staging)

    int tid = threadIdx.x;
    int lane = tid & 31;
    int warp = tid >> 5;
    int wm = warp & 1;
    int wn = warp >> 1;

    // Load W (128x128 fp32) -> fp16 smem once per block
    const float4* W4 = (const float4*)W;
    for (int i = tid; i < 4096; i += 256) {
        float4 v = W4[i];
        int r = i >> 5;
        int c = (i & 31) << 2;
        *(__half2*)(sW + r * LDH + c)     = __floats2half2_rn(v.x, v.y);
        *(__half2*)(sW + r * LDH + c + 2) = __floats2half2_rn(v.z, v.w);
    }

    const uint2* X2 = (const uint2*)g_Xh;

    for (int tile = blockIdx.x; tile < n_tiles; tile += gridDim.x) {
        // ---- Phase A: aggregate 8 nodes per warp into the smem agg tile ----
#pragma unroll 1
        for (int i8 = 0; i8 < 8; i8++) {
            int r = warp * 8 + i8;            // row in tile (0..63)
            int node = tile * 64 + r;
            float4 acc = make_float4(0.f, 0.f, 0.f, 0.f);
            if (node < N) {
                int2 mc = __ldg(&g_meta[node]);
                int s = mc.x, e = mc.x + mc.y;
                if (lane == 0) {
                    g_hist[node] = 0;                 // restore zero invariant
                    if (node == 0) g_hist[N + 1] = 0; // reset scan counter
                }
                int i = s;
                for (; i + 8 <= e; i += 8) {
                    uint4 q0 = *(const uint4*)(g_src + i);
                    uint4 q1 = *(const uint4*)(g_src + i + 4);
                    uint2 rr[8];
                    rr[0] = X2[(size_t)q0.x * 32 + lane];
                    rr[1] = X2[(size_t)q0.y * 32 + lane];
                    rr[2] = X2[(size_t)q0.z * 32 + lane];
                    rr[3] = X2[(size_t)q0.w * 32 + lane];
                    rr[4] = X2[(size_t)q1.x * 32 + lane];
                    rr[5] = X2[(size_t)q1.y * 32 + lane];
                    rr[6] = X2[(size_t)q1.z * 32 + lane];
                    rr[7] = X2[(size_t)q1.w * 32 + lane];
#pragma unroll
                    for (int j = 0; j < 8; j++) {
                        float2 lo = __half22float2(*(__half2*)&rr[j].x);
                        float2 hi = __half22float2(*(__half2*)&rr[j].y);
                        acc.x += lo.x; acc.y += lo.y; acc.z += hi.x; acc.w += hi.y;
                    }
                }
                if (i + 4 <= e) {
                    uint4 q0 = *(const uint4*)(g_src + i);
                    uint2 rr[4];
                    rr[0] = X2[(size_t)q0.x * 32 + lane];
                    rr[1] = X2[(size_t)q0.y * 32 + lane];
                    rr[2] = X2[(size_t)q0.z * 32 + lane];
                    rr[3] = X2[(size_t)q0.w * 32 + lane];
#pragma unroll
                    for (int j = 0; j < 4; j++) {
                        float2 lo = __half22float2(*(__half2*)&rr[j].x);
                        float2 hi = __half22float2(*(__half2*)&rr[j].y);
                        acc.x += lo.x; acc.y += lo.y; acc.z += hi.x; acc.w += hi.y;
                    }
                    i += 4;
                }
                for (; i < e; i++) {
                    uint2 r0 = X2[(size_t)g_src[i] * 32 + lane];
                    float2 lo = __half22float2(*(__half2*)&r0.x);
                    float2 hi = __half22float2(*(__half2*)&r0.y);
                    acc.x += lo.x; acc.y += lo.y; acc.z += hi.x; acc.w += hi.y;
                }
            }
            // write agg row (4 halves per lane, 8B, conflict-free)
            __half2 h0 = __floats2half2_rn(acc.x, acc.y);
            __half2 h1 = __floats2half2_rn(acc.z, acc.w);
            uint2 u;
            u.x = *(unsigned*)&h0;
            u.y = *(unsigned*)&h1;
            *(uint2*)(sAgg + r * LDH + lane * 4) = u;
        }
        __syncthreads();   // agg tile + sW visible to all warps

        // ---- Phase B: GEMM agg @ W ----
        wmma::fragment<wmma::accumulator, 16, 16, 16, float> acc[2][2];
#pragma unroll
        for (int mi = 0; mi < 2; mi++)
#pragma unroll
            for (int ni = 0; ni < 2; ni++)
                wmma::fill_fragment(acc[mi][ni], 0.0f);

#pragma unroll
        for (int kf = 0; kf < 8; kf++) {
            wmma::fragment<wmma::matrix_a, 16, 16, 16, __half, wmma::row_major> a0, a1;
            wmma::load_matrix_sync(a0, sAgg + (wm * 32 + 0)  * LDH + kf * 16, LDH);
            wmma::load_matrix_sync(a1, sAgg + (wm * 32 + 16) * LDH + kf * 16, LDH);
            wmma::fragment<wmma::matrix_b, 16, 16, 16, __half, wmma::row_major> b0, b1;
            wmma::load_matrix_sync(b0, sW + kf * 16 * LDH + wn * 32, LDH);
            wmma::load_matrix_sync(b1, sW + kf * 16 * LDH + wn * 32 + 16, LDH);
            wmma::mma_sync(acc[0][0], a0, b0, acc[0][0]);
            wmma::mma_sync(acc[0][1], a0, b1, acc[0][1]);
            wmma::mma_sync(acc[1][0], a1, b0, acc[1][0]);
            wmma::mma_sync(acc[1][1], a1, b1, acc[1][1]);
        }
        __syncthreads();   // all fragment loads done; reuse sAgg as staging

        // ---- Epilogue: stage fp32, add bias, STG.128 out ----
        float* epi = (float*)sAgg + warp * 320;   // 16x20 per warp, disjoint
        size_t row0 = (size_t)tile * 64 + wm * 32;
#pragma unroll
        for (int mi = 0; mi < 2; mi++) {
#pragma unroll
            for (int ni = 0; ni < 2; ni++) {
                wmma::store_matrix_sync(epi, acc[mi][ni], 20, wmma::mem_row_major);
                __syncwarp();
                int er = lane & 15;
                int eh = lane >> 4;
                size_t grow = row0 + mi * 16 + er;
                if (grow < (size_t)N) {
                    int col = wn * 32 + ni * 16 + eh * 8;
                    const float* src = epi + er * 20 + eh * 8;
                    float4 v0 = *(const float4*)(src);
                    float4 v1 = *(const float4*)(src + 4);
                    float4 b0 = *(const float4*)(bias + col);
                    float4 b1 = *(const float4*)(bias + col + 4);
                    v0.x += b0.x; v0.y += b0.y; v0.z += b0.z; v0.w += b0.w;
                    v1.x += b1.x; v1.y += b1.y; v1.z += b1.z; v1.w += b1.w;
                    *(float4*)(out + grow * 128 + col)     = v0;
                    *(float4*)(out + grow * 128 + col + 4) = v1;
                }
                __syncwarp();
            }
        }
        __syncthreads();   // before next tile's Phase A overwrites sAgg
    }
}

// ---------------------------------------------------------------------------
// Launch: fork (sort || convert), join, fused aggregate+GEMM.
// ---------------------------------------------------------------------------
extern "C" void kernel_launch(void* const* d_in, const int* in_sizes, int n_in,
                              void* d_out, int out_size) {
    const float* X    = (const float*)d_in[0];
    const int*   refA = (const int*)d_in[1];
    const int*   refB = (const int*)d_in[2];
    const float* W    = (const float*)d_in[3];
    const float* b    = (const float*)d_in[4];
    float* out = (float*)d_out;

    int N = in_sizes[0] / 128;   // 100000
    int E = in_sizes[1];         // 640000
    int NB = (N + 255) / 256;
    int n_tiles = (N + 63) / 64;

    // Fork side stream off the capture (legacy) stream
    cudaEventRecord(g_ss.fork, 0);
    cudaStreamWaitEvent(g_ss.s, g_ss.fork, 0);

    // --- Branch B (side stream): counting sort ---
    int ethreads8 = (E + 7) / 8;
    hist_kernel<<<(ethreads8 + 255) / 256, 256, 0, g_ss.s>>>(refB, E);
    scan_fused_kernel<<<NB, 256, 0, g_ss.s>>>(N);
    reorder_kernel<<<(ethreads8 + 255) / 256, 256, 0, g_ss.s>>>(refA, refB, E);
    cudaEventRecord(g_ss.join, g_ss.s);

    // --- Branch A (capture stream): X -> fp16 ---
    int total4 = N * 32;
    convert_kernel<<<(total4 + 255) / 256, 256>>>(X, total4);

    // --- Join, then fused aggregate + GEMM + bias ---
    cudaStreamWaitEvent(0, g_ss.join, 0);
    cudaFuncSetAttribute(fused_kernel,
                         cudaFuncAttributeMaxDynamicSharedMemorySize,
                         FUSED_SMEM_BYTES);
    fused_kernel<<<296, 256, FUSED_SMEM_BYTES>>>(W, b, out, n_tiles, N);
}

// round 14
// speedup vs baseline: 1.4961x; 1.4961x over previous
#include <cuda_runtime.h>
#include <cuda_fp16.h>
#include <cuda_bf16.h>
#include <mma.h>

using namespace nvcuda;

#define MAX_NODES 100000
#define MAX_EDGES 640000
// g_src capacity: edges + up-to-3 pad slots per node (16B-aligned regions)
#define SRC_CAP (MAX_EDGES + 4 * MAX_NODES)

// Scratch (device globals — allocation in kernel_launch is forbidden).
// g_hist must be all-zero at entry: zero-initialized at module load, restored
// to zero by accum_kernel every call (holds across graph replays).
__device__ __half g_Yh[(size_t)MAX_NODES * 128];        // Y = X@W fp16 (25.6 MB)
__device__ int    g_hist[MAX_NODES + 256];              // counts; [N+1] = base counter
__device__ int2   g_meta[MAX_NODES];                    // {aligned start, count}
__device__ int    g_cursor[MAX_NODES];
__device__ int    g_src[SRC_CAP];                       // sources grouped by dest

struct SideStream {
    cudaStream_t s;
    cudaEvent_t fork, join;
    SideStream() {
        cudaStreamCreateWithFlags(&s, cudaStreamNonBlocking);
        cudaEventCreateWithFlags(&fork, cudaEventDisableTiming);
        cudaEventCreateWithFlags(&join, cudaEventDisableTiming);
    }
};
static SideStream g_ss;

// ---------------------------------------------------------------------------
// Sort phase 1: histogram of destinations (8 edges/thread for atomic MLP)
// ---------------------------------------------------------------------------
__global__ void hist_kernel(const int* __restrict__ refB, int E) {
    int base = (blockIdx.x * blockDim.x + threadIdx.x) * 8;
    if (base + 7 < E) {
        int4 d0 = *(const int4*)(refB + base);
        int4 d1 = *(const int4*)(refB + base + 4);
        atomicAdd(&g_hist[d0.x], 1);
        atomicAdd(&g_hist[d0.y], 1);
        atomicAdd(&g_hist[d0.z], 1);
        atomicAdd(&g_hist[d0.w], 1);
        atomicAdd(&g_hist[d1.x], 1);
        atomicAdd(&g_hist[d1.y], 1);
        atomicAdd(&g_hist[d1.z], 1);
        atomicAdd(&g_hist[d1.w], 1);
    } else {
        for (int i = base; i < E; i++) atomicAdd(&g_hist[refB[i]], 1);
    }
}

// ---------------------------------------------------------------------------
// Sort phase 2 (fused scan): counts padded to multiples of 4 (16B-aligned
// regions); block total claims a base via atomicAdd on g_hist[N+1].
// Writes g_meta = {aligned start, actual count}.
// ---------------------------------------------------------------------------
__global__ __launch_bounds__(256)
void scan_fused_kernel(int N) {
    __shared__ int warp_pref[8];
    __shared__ int block_base;
    int t = threadIdx.x, lane = t & 31, wid = t >> 5;
    int node = blockIdx.x * 256 + t;
    int v = (node < N) ? g_hist[node] : 0;
    int vp = (v + 3) & ~3;

    int x = vp;
#pragma unroll
    for (int off = 1; off < 32; off <<= 1) {
        int y = __shfl_up_sync(0xFFFFFFFFu, x, off);
        if (lane >= off) x += y;
    }
    if (lane == 31) warp_pref[wid] = x;
    __syncthreads();
    if (wid == 0) {
        int ws = (lane < 8) ? warp_pref[lane] : 0;
        int wx = ws;
#pragma unroll
        for (int off = 1; off < 8; off <<= 1) {
            int y = __shfl_up_sync(0xFFFFFFFFu, wx, off);
            if (lane >= off) wx += y;
        }
        if (lane < 8) warp_pref[lane] = wx - ws;
        if (lane == 7) block_base = atomicAdd(&g_hist[N + 1], wx);
    }
    __syncthreads();
    if (node < N) {
        int start = block_base + warp_pref[wid] + x - vp;
        g_meta[node]   = make_int2(start, v);
        g_cursor[node] = start;
    }
}

// ---------------------------------------------------------------------------
// Sort phase 3: bucket reorder (8 edges/thread for atomic MLP)
// ---------------------------------------------------------------------------
__global__ void reorder_kernel(const int* __restrict__ refA,
                               const int* __restrict__ refB, int E) {
    int base = (blockIdx.x * blockDim.x + threadIdx.x) * 8;
    if (base + 7 < E) {
        int4 d0 = *(const int4*)(refB + base);
        int4 d1 = *(const int4*)(refB + base + 4);
        int4 a0 = *(const int4*)(refA + base);
        int4 a1 = *(const int4*)(refA + base + 4);
        int p0 = atomicAdd(&g_cursor[d0.x], 1);
        int p1 = atomicAdd(&g_cursor[d0.y], 1);
        int p2 = atomicAdd(&g_cursor[d0.z], 1);
        int p3 = atomicAdd(&g_cursor[d0.w], 1);
        int p4 = atomicAdd(&g_cursor[d1.x], 1);
        int p5 = atomicAdd(&g_cursor[d1.y], 1);
        int p6 = atomicAdd(&g_cursor[d1.z], 1);
        int p7 = atomicAdd(&g_cursor[d1.w], 1);
        g_src[p0] = a0.x;
        g_src[p1] = a0.y;
        g_src[p2] = a0.z;
        g_src[p3] = a0.w;
        g_src[p4] = a1.x;
        g_src[p5] = a1.y;
        g_src[p6] = a1.z;
        g_src[p7] = a1.w;
    } else {
        for (int i = base; i < E; i++) {
            int pos = atomicAdd(&g_cursor[refB[i]], 1);
            g_src[pos] = refA[i];
        }
    }
}

// ---------------------------------------------------------------------------
// GEMM: Y = X @ W, fp16 wmma (m16n16k16), fp32 accum, fp16 output via padded
// smem staging (round-8 version: NO predication; tail handled by tail kernel).
// 256 threads / 8 warps; A tiles (64x128) double-buffered, register prefetch.
// ---------------------------------------------------------------------------
#define LDH 136   // padded leading dim (halves)
#define SW_HALFS   (128 * LDH)
#define SA_HALFS   (64 * LDH)
#define GEMM_SMEM_BYTES ((SW_HALFS + 2 * SA_HALFS) * 2)

__global__ __launch_bounds__(256, 2)
void gemm_f16_kernel(const float* __restrict__ X,
                     const float* __restrict__ W,
                     int n_mtiles) {   // tiles of 64 rows (floor)
    extern __shared__ __half smem[];
    __half* sW  = smem;                       // 128 x LDH
    __half* sA0 = smem + SW_HALFS;            // 64 x LDH
    __half* sA1 = sA0 + SA_HALFS;             // 64 x LDH

    int tid = threadIdx.x;
    int lane = tid & 31;
    int warp = tid >> 5;
    int wm = warp & 1;      // 32-row half of the 64-row tile
    int wn = warp >> 1;     // 32-col quarter

    // Load W (128x128 fp32) -> fp16 smem (once per block)
    const float4* W4 = (const float4*)W;
    for (int i = tid; i < 4096; i += 256) {
        float4 v = W4[i];
        int r = i >> 5;
        int c = (i & 31) << 2;
        *(__half2*)(sW + r * LDH + c)     = __floats2half2_rn(v.x, v.y);
        *(__half2*)(sW + r * LDH + c + 2) = __floats2half2_rn(v.z, v.w);
    }

    // Prefetch first A tile into registers, stage into sA0
    float4 pf[8];
    int mt = blockIdx.x;
    if (mt < n_mtiles) {
        const float4* X4 = (const float4*)(X + (size_t)mt * 64 * 128);
#pragma unroll
        for (int j = 0; j < 8; j++) pf[j] = X4[tid + j * 256];
#pragma unroll
        for (int j = 0; j < 8; j++) {
            int i = tid + j * 256;
            int r = i >> 5;
            int c = (i & 31) << 2;
            *(__half2*)(sA0 + r * LDH + c)     = __floats2half2_rn(pf[j].x, pf[j].y);
            *(__half2*)(sA0 + r * LDH + c + 2) = __floats2half2_rn(pf[j].z, pf[j].w);
        }
    }
    __syncthreads();

    int buf = 0;
    for (; mt < n_mtiles; mt += gridDim.x) {
        int nxt = mt + gridDim.x;
        if (nxt < n_mtiles) {
            const float4* X4 = (const float4*)(X + (size_t)nxt * 64 * 128);
#pragma unroll
            for (int j = 0; j < 8; j++) pf[j] = X4[tid + j * 256];
        }

        __half* sAc = buf ? sA1 : sA0;
        wmma::fragment<wmma::accumulator, 16, 16, 16, float> acc[2][2];
#pragma unroll
        for (int mi = 0; mi < 2; mi++)
#pragma unroll
            for (int ni = 0; ni < 2; ni++)
                wmma::fill_fragment(acc[mi][ni], 0.0f);

#pragma unroll
        for (int kf = 0; kf < 8; kf++) {
            wmma::fragment<wmma::matrix_a, 16, 16, 16, __half, wmma::row_major> a0, a1;
            wmma::load_matrix_sync(a0, sAc + (wm * 32 + 0)  * LDH + kf * 16, LDH);
            wmma::load_matrix_sync(a1, sAc + (wm * 32 + 16) * LDH + kf * 16, LDH);
            wmma::fragment<wmma::matrix_b, 16, 16, 16, __half, wmma::row_major> b0, b1;
            wmma::load_matrix_sync(b0, sW + kf * 16 * LDH + wn * 32, LDH);
            wmma::load_matrix_sync(b1, sW + kf * 16 * LDH + wn * 32 + 16, LDH);
            wmma::mma_sync(acc[0][0], a0, b0, acc[0][0]);
            wmma::mma_sync(acc[0][1], a0, b1, acc[0][1]);
            wmma::mma_sync(acc[1][0], a1, b0, acc[1][0]);
            wmma::mma_sync(acc[1][1], a1, b1, acc[1][1]);
        }
        __syncthreads();   // all warps done reading sA[buf]; reuse as scratch

        // Epilogue: fp32 staging (ldm=20, per-warp disjoint), fp16 STG.128
        float* epi = (float*)sAc + warp * 320;
        size_t row0 = (size_t)mt * 64 + wm * 32;
#pragma unroll
        for (int mi = 0; mi < 2; mi++) {
#pragma unroll
            for (int ni = 0; ni < 2; ni++) {
                wmma::store_matrix_sync(epi, acc[mi][ni], 20, wmma::mem_row_major);
                __syncwarp();
                int er = lane & 15;
                int eh = lane >> 4;
                const float* src = epi + er * 20 + eh * 8;
                float4 v0 = *(const float4*)(src);
                float4 v1 = *(const float4*)(src + 4);
                __half2 h[4];
                h[0] = __floats2half2_rn(v0.x, v0.y);
                h[1] = __floats2half2_rn(v0.z, v0.w);
                h[2] = __floats2half2_rn(v1.x, v1.y);
                h[3] = __floats2half2_rn(v1.z, v1.w);
                *(uint4*)(g_Yh + (row0 + mi * 16 + er) * 128 +
                          wn * 32 + ni * 16 + eh * 8) = *(uint4*)h;
                __syncwarp();
            }
        }

        // Stage prefetched tile into the other buffer
        if (nxt < n_mtiles) {
            __half* dst = buf ? sA0 : sA1;
#pragma unroll
            for (int j = 0; j < 8; j++) {
                int i = tid + j * 256;
                int r = i >> 5;
                int c = (i & 31) << 2;
                *(__half2*)(dst + r * LDH + c)     = __floats2half2_rn(pf[j].x, pf[j].y);
                *(__half2*)(dst + r * LDH + c + 2) = __floats2half2_rn(pf[j].z, pf[j].w);
            }
        }
        __syncthreads();
        buf ^= 1;
    }
}

// Scalar tail for rows not covered by 64-row tiles (32 rows at N=100000).
// Runs FIRST on the side stream so its latency hides under the main GEMM.
__global__ void gemm_tail_kernel(const float* __restrict__ X,
                                 const float* __restrict__ W,
                                 int row_start, int n_rows) {
    int r = row_start + blockIdx.x;
    if ((int)blockIdx.x >= n_rows) return;
    int j = threadIdx.x;
    float acc = 0.0f;
#pragma unroll 8
    for (int k = 0; k < 128; k++)
        acc += X[(size_t)r * 128 + k] * W[(size_t)k * 128 + j];
    g_Yh[(size_t)r * 128 + j] = __float2half_rn(acc);
}

// ---------------------------------------------------------------------------
// Accumulate: one warp per destination node. 16B-aligned node regions ->
// broadcast uint4 index loads (1 LDG.128 per 4 edges). fp16 gather, fp32
// accumulation, bias folded in. Restores g_hist=0 invariant.
// ---------------------------------------------------------------------------
__global__ __launch_bounds__(256)
void accum_kernel(const float* __restrict__ b, float* __restrict__ out, int N) {
    int node = (blockIdx.x * blockDim.x + threadIdx.x) >> 5;
    int lane = threadIdx.x & 31;
    if (node >= N) return;
    int2 mc = __ldg(&g_meta[node]);   // {aligned start, count}
    int s = mc.x;
    int e = s + mc.y;
    if (lane == 0) {
        g_hist[node] = 0;                       // restore zero invariant
        if (node == 0) g_hist[N + 1] = 0;       // reset scan base counter
    }

    const uint2* Y2 = (const uint2*)g_Yh;
    float4 acc = make_float4(0.f, 0.f, 0.f, 0.f);
    int i = s;
    for (; i + 8 <= e; i += 8) {
        uint4 q0 = *(const uint4*)(g_src + i);
        uint4 q1 = *(const uint4*)(g_src + i + 4);
        uint2 r[8];
        r[0] = Y2[(size_t)q0.x * 32 + lane];
        r[1] = Y2[(size_t)q0.y * 32 + lane];
        r[2] = Y2[(size_t)q0.z * 32 + lane];
        r[3] = Y2[(size_t)q0.w * 32 + lane];
        r[4] = Y2[(size_t)q1.x * 32 + lane];
        r[5] = Y2[(size_t)q1.y * 32 + lane];
        r[6] = Y2[(size_t)q1.z * 32 + lane];
        r[7] = Y2[(size_t)q1.w * 32 + lane];
#pragma unroll
        for (int j = 0; j < 8; j++) {
            float2 lo = __half22float2(*(__half2*)&r[j].x);
            float2 hi = __half22float2(*(__half2*)&r[j].y);
            acc.x += lo.x; acc.y += lo.y; acc.z += hi.x; acc.w += hi.y;
        }
    }
    if (i + 4 <= e) {
        uint4 q0 = *(const uint4*)(g_src + i);
        uint2 r[4];
        r[0] = Y2[(size_t)q0.x * 32 + lane];
        r[1] = Y2[(size_t)q0.y * 32 + lane];
        r[2] = Y2[(size_t)q0.z * 32 + lane];
        r[3] = Y2[(size_t)q0.w * 32 + lane];
#pragma unroll
        for (int j = 0; j < 4; j++) {
            float2 lo = __half22float2(*(__half2*)&r[j].x);
            float2 hi = __half22float2(*(__half2*)&r[j].y);
            acc.x += lo.x; acc.y += lo.y; acc.z += hi.x; acc.w += hi.y;
        }
        i += 4;
    }
    for (; i < e; i++) {
        uint2 r0 = Y2[(size_t)g_src[i] * 32 + lane];
        float2 lo = __half22float2(*(__half2*)&r0.x);
        float2 hi = __half22float2(*(__half2*)&r0.y);
        acc.x += lo.x; acc.y += lo.y; acc.z += hi.x; acc.w += hi.y;
    }

    float4 bv = ((const float4*)b)[lane];
    acc.x += bv.x; acc.y += bv.y; acc.z += bv.z; acc.w += bv.w;
    ((float4*)(out + (size_t)node * 128))[lane] = acc;
}

// ---------------------------------------------------------------------------
// Launch: two parallel branches (tail + sort || GEMM), join, accum.
// ---------------------------------------------------------------------------
extern "C" void kernel_launch(void* const* d_in, const int* in_sizes, int n_in,
                              void* d_out, int out_size) {
    const float* X    = (const float*)d_in[0];
    const int*   refA = (const int*)d_in[1];
    const int*   refB = (const int*)d_in[2];
    const float* W    = (const float*)d_in[3];
    const float* b    = (const float*)d_in[4];
    float* out = (float*)d_out;

    int N = in_sizes[0] / 128;   // 100000
    int E = in_sizes[1];         // 640000
    int NB = (N + 255) / 256;
    int n_mtiles = N / 64;       // floor; tail kernel covers remainder
    int tail = N - n_mtiles * 64;

    // Fork side stream off the capture (legacy) stream
    cudaEventRecord(g_ss.fork, 0);
    cudaStreamWaitEvent(g_ss.s, g_ss.fork, 0);

    // --- Branch B (side stream): GEMM tail FIRST (hidden), then sort ---
    if (tail > 0)
        gemm_tail_kernel<<<tail, 128, 0, g_ss.s>>>(X, W, n_mtiles * 64, tail);
    int ethreads8 = (E + 7) / 8;
    hist_kernel<<<(ethreads8 + 255) / 256, 256, 0, g_ss.s>>>(refB, E);
    scan_fused_kernel<<<NB, 256, 0, g_ss.s>>>(N);
    reorder_kernel<<<(ethreads8 + 255) / 256, 256, 0, g_ss.s>>>(refA, refB, E);
    cudaEventRecord(g_ss.join, g_ss.s);

    // --- Branch A (capture stream): Y = X @ W (fp16 wmma, unpredicated) ---
    cudaFuncSetAttribute(gemm_f16_kernel,
                         cudaFuncAttributeMaxDynamicSharedMemorySize,
                         GEMM_SMEM_BYTES);
    gemm_f16_kernel<<<296, 256, GEMM_SMEM_BYTES>>>(X, W, n_mtiles);

    // --- Join, then per-node register accumulation + bias ---
    cudaStreamWaitEvent(0, g_ss.join, 0);
    accum_kernel<<<(N * 32 + 255) / 256, 256>>>(b, out, N);
}

// round 15
// speedup vs baseline: 1.6099x; 1.0761x over previous
#include <cuda_runtime.h>
#include <cuda_fp16.h>
#include <cuda_bf16.h>
#include <mma.h>

using namespace nvcuda;

#define MAX_NODES 100000
#define MAX_EDGES 640000
// g_src capacity: edges + up-to-3 pad slots per node (16B-aligned regions)
#define SRC_CAP (MAX_EDGES + 4 * MAX_NODES)

// Scratch (device globals — allocation in kernel_launch is forbidden).
// g_hist must be all-zero at entry: zero-initialized at module load, restored
// to zero by accum_kernel every call (holds across graph replays).
__device__ __half g_Yh[(size_t)MAX_NODES * 128];        // Y = X@W fp16 (25.6 MB)
__device__ int    g_hist[MAX_NODES + 256];              // counts; [N+1] = base counter
__device__ int2   g_meta[MAX_NODES];                    // {aligned start, count}
__device__ int    g_cursor[MAX_NODES];
__device__ int    g_src[SRC_CAP];                       // sources grouped by dest

struct SideStream {
    cudaStream_t s;
    cudaEvent_t fork, join;
    SideStream() {
        cudaStreamCreateWithFlags(&s, cudaStreamNonBlocking);
        cudaEventCreateWithFlags(&fork, cudaEventDisableTiming);
        cudaEventCreateWithFlags(&join, cudaEventDisableTiming);
    }
};
static SideStream g_ss;

// ---------------------------------------------------------------------------
// Sort phase 1: histogram of destinations (8 edges/thread for atomic MLP)
// ---------------------------------------------------------------------------
__global__ void hist_kernel(const int* __restrict__ refB, int E) {
    int base = (blockIdx.x * blockDim.x + threadIdx.x) * 8;
    if (base + 7 < E) {
        int4 d0 = *(const int4*)(refB + base);
        int4 d1 = *(const int4*)(refB + base + 4);
        atomicAdd(&g_hist[d0.x], 1);
        atomicAdd(&g_hist[d0.y], 1);
        atomicAdd(&g_hist[d0.z], 1);
        atomicAdd(&g_hist[d0.w], 1);
        atomicAdd(&g_hist[d1.x], 1);
        atomicAdd(&g_hist[d1.y], 1);
        atomicAdd(&g_hist[d1.z], 1);
        atomicAdd(&g_hist[d1.w], 1);
    } else {
        for (int i = base; i < E; i++) atomicAdd(&g_hist[refB[i]], 1);
    }
}

// ---------------------------------------------------------------------------
// Sort phase 2 (fused scan): counts padded to multiples of 4 (16B-aligned
// regions); block total claims a base via atomicAdd on g_hist[N+1].
// Writes g_meta = {aligned start, actual count}.
// ---------------------------------------------------------------------------
__global__ __launch_bounds__(256)
void scan_fused_kernel(int N) {
    __shared__ int warp_pref[8];
    __shared__ int block_base;
    int t = threadIdx.x, lane = t & 31, wid = t >> 5;
    int node = blockIdx.x * 256 + t;
    int v = (node < N) ? g_hist[node] : 0;
    int vp = (v + 3) & ~3;

    int x = vp;
#pragma unroll
    for (int off = 1; off < 32; off <<= 1) {
        int y = __shfl_up_sync(0xFFFFFFFFu, x, off);
        if (lane >= off) x += y;
    }
    if (lane == 31) warp_pref[wid] = x;
    __syncthreads();
    if (wid == 0) {
        int ws = (lane < 8) ? warp_pref[lane] : 0;
        int wx = ws;
#pragma unroll
        for (int off = 1; off < 8; off <<= 1) {
            int y = __shfl_up_sync(0xFFFFFFFFu, wx, off);
            if (lane >= off) wx += y;
        }
        if (lane < 8) warp_pref[lane] = wx - ws;
        if (lane == 7) block_base = atomicAdd(&g_hist[N + 1], wx);
    }
    __syncthreads();
    if (node < N) {
        int start = block_base + warp_pref[wid] + x - vp;
        g_meta[node]   = make_int2(start, v);
        g_cursor[node] = start;
    }
}

// ---------------------------------------------------------------------------
// Sort phase 3: bucket reorder (8 edges/thread for atomic MLP)
// ---------------------------------------------------------------------------
__global__ void reorder_kernel(const int* __restrict__ refA,
                               const int* __restrict__ refB, int E) {
    int base = (blockIdx.x * blockDim.x + threadIdx.x) * 8;
    if (base + 7 < E) {
        int4 d0 = *(const int4*)(refB + base);
        int4 d1 = *(const int4*)(refB + base + 4);
        int4 a0 = *(const int4*)(refA + base);
        int4 a1 = *(const int4*)(refA + base + 4);
        int p0 = atomicAdd(&g_cursor[d0.x], 1);
        int p1 = atomicAdd(&g_cursor[d0.y], 1);
        int p2 = atomicAdd(&g_cursor[d0.z], 1);
        int p3 = atomicAdd(&g_cursor[d0.w], 1);
        int p4 = atomicAdd(&g_cursor[d1.x], 1);
        int p5 = atomicAdd(&g_cursor[d1.y], 1);
        int p6 = atomicAdd(&g_cursor[d1.z], 1);
        int p7 = atomicAdd(&g_cursor[d1.w], 1);
        g_src[p0] = a0.x;
        g_src[p1] = a0.y;
        g_src[p2] = a0.z;
        g_src[p3] = a0.w;
        g_src[p4] = a1.x;
        g_src[p5] = a1.y;
        g_src[p6] = a1.z;
        g_src[p7] = a1.w;
    } else {
        for (int i = base; i < E; i++) {
            int pos = atomicAdd(&g_cursor[refB[i]], 1);
            g_src[pos] = refA[i];
        }
    }
}

// ---------------------------------------------------------------------------
// GEMM: Y = X @ W, fp16 wmma (m16n16k16), fp32 accum, fp16 output via padded
// smem staging. 1562/1563 tiles take the unpredicated round-8 fast path;
// ONLY the last (ragged) tile takes the bounds-checked path.
// 256 threads / 8 warps; A tiles (64x128) double-buffered, register prefetch.
// ---------------------------------------------------------------------------
#define LDH 136   // padded leading dim (halves)
#define SW_HALFS   (128 * LDH)
#define SA_HALFS   (64 * LDH)
#define GEMM_SMEM_BYTES ((SW_HALFS + 2 * SA_HALFS) * 2)

__device__ __forceinline__ void stage_tile_fast(const float* __restrict__ X,
                                                __half* dst, int mt, int tid,
                                                float4* pf) {
    const float4* X4 = (const float4*)(X + (size_t)mt * 64 * 128);
#pragma unroll
    for (int j = 0; j < 8; j++) pf[j] = X4[tid + j * 256];
#pragma unroll
    for (int j = 0; j < 8; j++) {
        int i = tid + j * 256;
        int r = i >> 5;
        int c = (i & 31) << 2;
        *(__half2*)(dst + r * LDH + c)     = __floats2half2_rn(pf[j].x, pf[j].y);
        *(__half2*)(dst + r * LDH + c + 2) = __floats2half2_rn(pf[j].z, pf[j].w);
    }
}

__device__ __forceinline__ void stage_tile_pred(const float* __restrict__ X,
                                                __half* dst, int mt, int tid,
                                                int N) {
    const float4* X4 = (const float4*)X;
    size_t base4 = (size_t)mt * 64 * 32;
    size_t lim4 = (size_t)N * 32;
    const float4 z = make_float4(0.f, 0.f, 0.f, 0.f);
#pragma unroll
    for (int j = 0; j < 8; j++) {
        size_t idx = base4 + tid + j * 256;
        float4 v = (idx < lim4) ? X4[idx] : z;
        int i = tid + j * 256;
        int r = i >> 5;
        int c = (i & 31) << 2;
        *(__half2*)(dst + r * LDH + c)     = __floats2half2_rn(v.x, v.y);
        *(__half2*)(dst + r * LDH + c + 2) = __floats2half2_rn(v.z, v.w);
    }
}

__global__ __launch_bounds__(256, 2)
void gemm_f16_kernel(const float* __restrict__ X,
                     const float* __restrict__ W,
                     int n_mtiles, int N) {   // n_mtiles = ceil(N/64)
    extern __shared__ __half smem[];
    __half* sW  = smem;                       // 128 x LDH
    __half* sA0 = smem + SW_HALFS;            // 64 x LDH
    __half* sA1 = sA0 + SA_HALFS;             // 64 x LDH

    int tid = threadIdx.x;
    int lane = tid & 31;
    int warp = tid >> 5;
    int wm = warp & 1;      // 32-row half of the 64-row tile
    int wn = warp >> 1;     // 32-col quarter
    int last = n_mtiles - 1;
    bool ragged = (N & 63) != 0;

    // Load W (128x128 fp32) -> fp16 smem (once per block)
    const float4* W4 = (const float4*)W;
    for (int i = tid; i < 4096; i += 256) {
        float4 v = W4[i];
        int r = i >> 5;
        int c = (i & 31) << 2;
        *(__half2*)(sW + r * LDH + c)     = __floats2half2_rn(v.x, v.y);
        *(__half2*)(sW + r * LDH + c + 2) = __floats2half2_rn(v.z, v.w);
    }

    // Prefetch + stage first A tile into sA0
    float4 pf[8];
    int mt = blockIdx.x;
    if (mt < n_mtiles) {
        if (mt == last && ragged) stage_tile_pred(X, sA0, mt, tid, N);
        else                       stage_tile_fast(X, sA0, mt, tid, pf);
    }
    __syncthreads();

    int buf = 0;
    for (; mt < n_mtiles; mt += gridDim.x) {
        int nxt = mt + gridDim.x;
        bool nxt_fast = (nxt < n_mtiles) && !(nxt == last && ragged);
        if (nxt_fast) {   // fast prefetch into registers (common case)
            const float4* X4 = (const float4*)(X + (size_t)nxt * 64 * 128);
#pragma unroll
            for (int j = 0; j < 8; j++) pf[j] = X4[tid + j * 256];
        }

        __half* sAc = buf ? sA1 : sA0;
        wmma::fragment<wmma::accumulator, 16, 16, 16, float> acc[2][2];
#pragma unroll
        for (int mi = 0; mi < 2; mi++)
#pragma unroll
            for (int ni = 0; ni < 2; ni++)
                wmma::fill_fragment(acc[mi][ni], 0.0f);

#pragma unroll
        for (int kf = 0; kf < 8; kf++) {
            wmma::fragment<wmma::matrix_a, 16, 16, 16, __half, wmma::row_major> a0, a1;
            wmma::load_matrix_sync(a0, sAc + (wm * 32 + 0)  * LDH + kf * 16, LDH);
            wmma::load_matrix_sync(a1, sAc + (wm * 32 + 16) * LDH + kf * 16, LDH);
            wmma::fragment<wmma::matrix_b, 16, 16, 16, __half, wmma::row_major> b0, b1;
            wmma::load_matrix_sync(b0, sW + kf * 16 * LDH + wn * 32, LDH);
            wmma::load_matrix_sync(b1, sW + kf * 16 * LDH + wn * 32 + 16, LDH);
            wmma::mma_sync(acc[0][0], a0, b0, acc[0][0]);
            wmma::mma_sync(acc[0][1], a0, b1, acc[0][1]);
            wmma::mma_sync(acc[1][0], a1, b0, acc[1][0]);
            wmma::mma_sync(acc[1][1], a1, b1, acc[1][1]);
        }
        __syncthreads();   // all warps done reading sA[buf]; reuse as scratch

        // Epilogue: fp32 staging (ldm=20, per-warp disjoint), fp16 STG.128
        float* epi = (float*)sAc + warp * 320;
        size_t row0 = (size_t)mt * 64 + wm * 32;
        bool tile_fast = !(mt == last && ragged);
#pragma unroll
        for (int mi = 0; mi < 2; mi++) {
#pragma unroll
            for (int ni = 0; ni < 2; ni++) {
                wmma::store_matrix_sync(epi, acc[mi][ni], 20, wmma::mem_row_major);
                __syncwarp();
                int er = lane & 15;
                int eh = lane >> 4;
                size_t grow = row0 + mi * 16 + er;
                if (tile_fast || grow < (size_t)N) {
                    const float* src = epi + er * 20 + eh * 8;
                    float4 v0 = *(const float4*)(src);
                    float4 v1 = *(const float4*)(src + 4);
                    __half2 h[4];
                    h[0] = __floats2half2_rn(v0.x, v0.y);
                    h[1] = __floats2half2_rn(v0.z, v0.w);
                    h[2] = __floats2half2_rn(v1.x, v1.y);
                    h[3] = __floats2half2_rn(v1.z, v1.w);
                    *(uint4*)(g_Yh + grow * 128 +
                              wn * 32 + ni * 16 + eh * 8) = *(uint4*)h;
                }
                __syncwarp();
            }
        }

        // Stage next tile into the other buffer
        if (nxt < n_mtiles) {
            __half* dst = buf ? sA0 : sA1;
            if (nxt_fast) {
#pragma unroll
                for (int j = 0; j < 8; j++) {
                    int i = tid + j * 256;
                    int r = i >> 5;
                    int c = (i & 31) << 2;
                    *(__half2*)(dst + r * LDH + c)     = __floats2half2_rn(pf[j].x, pf[j].y);
                    *(__half2*)(dst + r * LDH + c + 2) = __floats2half2_rn(pf[j].z, pf[j].w);
                }
            } else {
                stage_tile_pred(X, dst, nxt, tid, N);
            }
        }
        __syncthreads();
        buf ^= 1;
    }
}

// ---------------------------------------------------------------------------
// Accumulate: one warp per destination node. 16B-aligned node regions ->
// broadcast uint4 index loads (1 LDG.128 per 4 edges). fp16 gather, fp32
// accumulation, bias folded in. Restores g_hist=0 invariant.
// ---------------------------------------------------------------------------
__global__ __launch_bounds__(256)
void accum_kernel(const float* __restrict__ b, float* __restrict__ out, int N) {
    int node = (blockIdx.x * blockDim.x + threadIdx.x) >> 5;
    int lane = threadIdx.x & 31;
    if (node >= N) return;
    int2 mc = __ldg(&g_meta[node]);   // {aligned start, count}
    int s = mc.x;
    int e = s + mc.y;
    if (lane == 0) {
        g_hist[node] = 0;                       // restore zero invariant
        if (node == 0) g_hist[N + 1] = 0;       // reset scan base counter
    }

    const uint2* Y2 = (const uint2*)g_Yh;
    float4 acc = make_float4(0.f, 0.f, 0.f, 0.f);
    int i = s;
    for (; i + 8 <= e; i += 8) {
        uint4 q0 = *(const uint4*)(g_src + i);
        uint4 q1 = *(const uint4*)(g_src + i + 4);
        uint2 r[8];
        r[0] = Y2[(size_t)q0.x * 32 + lane];
        r[1] = Y2[(size_t)q0.y * 32 + lane];
        r[2] = Y2[(size_t)q0.z * 32 + lane];
        r[3] = Y2[(size_t)q0.w * 32 + lane];
        r[4] = Y2[(size_t)q1.x * 32 + lane];
        r[5] = Y2[(size_t)q1.y * 32 + lane];
        r[6] = Y2[(size_t)q1.z * 32 + lane];
        r[7] = Y2[(size_t)q1.w * 32 + lane];
#pragma unroll
        for (int j = 0; j < 8; j++) {
            float2 lo = __half22float2(*(__half2*)&r[j].x);
            float2 hi = __half22float2(*(__half2*)&r[j].y);
            acc.x += lo.x; acc.y += lo.y; acc.z += hi.x; acc.w += hi.y;
        }
    }
    if (i + 4 <= e) {
        uint4 q0 = *(const uint4*)(g_src + i);
        uint2 r[4];
        r[0] = Y2[(size_t)q0.x * 32 + lane];
        r[1] = Y2[(size_t)q0.y * 32 + lane];
        r[2] = Y2[(size_t)q0.z * 32 + lane];
        r[3] = Y2[(size_t)q0.w * 32 + lane];
#pragma unroll
        for (int j = 0; j < 4; j++) {
            float2 lo = __half22float2(*(__half2*)&r[j].x);
            float2 hi = __half22float2(*(__half2*)&r[j].y);
            acc.x += lo.x; acc.y += lo.y; acc.z += hi.x; acc.w += hi.y;
        }
        i += 4;
    }
    for (; i < e; i++) {
        uint2 r0 = Y2[(size_t)g_src[i] * 32 + lane];
        float2 lo = __half22float2(*(__half2*)&r0.x);
        float2 hi = __half22float2(*(__half2*)&r0.y);
        acc.x += lo.x; acc.y += lo.y; acc.z += hi.x; acc.w += hi.y;
    }

    float4 bv = ((const float4*)b)[lane];
    acc.x += bv.x; acc.y += bv.y; acc.z += bv.z; acc.w += bv.w;
    ((float4*)(out + (size_t)node * 128))[lane] = acc;
}

// ---------------------------------------------------------------------------
// Launch: two parallel branches (sort || GEMM), join, accum.
// ---------------------------------------------------------------------------
extern "C" void kernel_launch(void* const* d_in, const int* in_sizes, int n_in,
                              void* d_out, int out_size) {
    const float* X    = (const float*)d_in[0];
    const int*   refA = (const int*)d_in[1];
    const int*   refB = (const int*)d_in[2];
    const float* W    = (const float*)d_in[3];
    const float* b    = (const float*)d_in[4];
    float* out = (float*)d_out;

    int N = in_sizes[0] / 128;   // 100000
    int E = in_sizes[1];         // 640000
    int NB = (N + 255) / 256;
    int n_mtiles = (N + 63) / 64;   // ragged last tile handled in-kernel

    // Fork side stream off the capture (legacy) stream
    cudaEventRecord(g_ss.fork, 0);
    cudaStreamWaitEvent(g_ss.s, g_ss.fork, 0);

    // --- Branch B (side stream): counting sort only (fully hidden) ---
    int ethreads8 = (E + 7) / 8;
    hist_kernel<<<(ethreads8 + 255) / 256, 256, 0, g_ss.s>>>(refB, E);
    scan_fused_kernel<<<NB, 256, 0, g_ss.s>>>(N);
    reorder_kernel<<<(ethreads8 + 255) / 256, 256, 0, g_ss.s>>>(refA, refB, E);
    cudaEventRecord(g_ss.join, g_ss.s);

    // --- Branch A (capture stream): Y = X @ W (fp16 wmma) ---
    cudaFuncSetAttribute(gemm_f16_kernel,
                         cudaFuncAttributeMaxDynamicSharedMemorySize,
                         GEMM_SMEM_BYTES);
    gemm_f16_kernel<<<296, 256, GEMM_SMEM_BYTES>>>(X, W, n_mtiles, N);

    // --- Join, then per-node register accumulation + bias ---
    cudaStreamWaitEvent(0, g_ss.join, 0);
    accum_kernel<<<(N * 32 + 255) / 256, 256>>>(b, out, N);
}